// round 14
// baseline (speedup 1.0000x reference)
#include <cuda_runtime.h>
#include <math.h>

// Problem constants
constexpr int B = 64;
constexpr int T = 512;
constexpr int E = 256;
constexpr int H = 512;
constexpr int K = 24;
constexpr int G = 4 * H;          // 2048
constexpr int H2 = 2 * H;         // 1024
constexpr int START_TAG = 22;
constexpr int STOP_TAG = 23;
constexpr float NEG = -10000.0f;
constexpr int M_ROWS = B * T;     // 32768

constexpr int NBLK = 128;         // persistent recurrence blocks (64 per dir)
constexpr int WKP = 36;           // ws row stride (floats)

// ------------------------- device scratch (static, no allocs) ----------------
__device__ float g_x[B * T * E];
__device__ float g_xg[2][T * G * B];          // [dir][(t*G+n)*B + b]
__device__ float g_h0[B * T * H2];
__device__ float g_h1[B * T * H2];
__device__ float g_hbuf[2][2][H * B];         // [dir][parity][k*64+b]
__device__ float g_feats[B * T * K];
__device__ unsigned g_barcnt2[2];
__device__ unsigned g_bargen2[2];

// ------------------------- small helpers -------------------------------------
static __device__ __forceinline__ unsigned smem_u32(const void* p) {
    unsigned r;
    asm("{ .reg .u64 t; cvta.to.shared.u64 t, %1; cvt.u32.u64 %0, t; }"
        : "=r"(r) : "l"(p));
    return r;
}
static __device__ __forceinline__ void cp_async16(unsigned dst, const void* src) {
    asm volatile("cp.async.cg.shared.global [%0], [%1], 16;\n" :: "r"(dst), "l"(src));
}
static __device__ __forceinline__ void cp_commit() {
    asm volatile("cp.async.commit_group;\n" ::: "memory");
}
template <int N>
static __device__ __forceinline__ void cp_wait() {
    asm volatile("cp.async.wait_group %0;\n" :: "n"(N) : "memory");
}

// packed f32x2 helpers
static __device__ __forceinline__ unsigned long long pack2(float x, float y) {
    unsigned long long r;
    asm("mov.b64 %0, {%1, %2};" : "=l"(r) : "f"(x), "f"(y));
    return r;
}
static __device__ __forceinline__ void fma2(unsigned long long& d,
                                            unsigned long long a,
                                            unsigned long long b) {
    asm("fma.rn.f32x2 %0, %1, %2, %3;" : "=l"(d) : "l"(a), "l"(b), "l"(d));
}
static __device__ __forceinline__ float2 unpack2(unsigned long long v) {
    float2 f;
    asm("mov.b64 {%0, %1}, %2;" : "=f"(f.x), "=f"(f.y) : "l"(v));
    return f;
}

// ------------------------- embedding lookup ----------------------------------
__global__ void embed_kernel(const int* __restrict__ sentence,
                             const float* __restrict__ embed) {
    int i = blockIdx.x * blockDim.x + threadIdx.x;
    if (i >= B * T * E) return;
    int e = i % E;
    int bt = i / E;
    g_x[i] = embed[(long long)sentence[bt] * E + e];
}

// ------------------------- big GEMM: xg_t = A * W^T + bias -------------------
__global__ __launch_bounds__(256, 2)
void gemm_bias_kernel(int a_sel, const float* __restrict__ W,
                      const float* __restrict__ bias, int c_dir, int Kd) {
    const float* __restrict__ A = a_sel ? g_h0 : g_x;
    float* __restrict__ C = g_xg[c_dir];

    __shared__ float As[2][16][132];
    __shared__ float Ws[2][16][132];

    int n0 = blockIdx.x * 128;
    int m0 = blockIdx.y * 128;
    int tid = threadIdx.x;
    int tx = tid & 15;
    int ty = tid >> 4;
    int tm0 = ty * 8;
    int tn0 = tx * 8;

    int lrow0 = (tid * 2) >> 2;
    int lkc0 = (tid * 2) & 3;
    int lrow1 = (tid * 2 + 1) >> 2;
    int lkc1 = (tid * 2 + 1) & 3;

    unsigned long long acc2[8][4] = {};
    float4 ra0, ra1, rw0, rw1;

    ra0 = *(const float4*)&A[(size_t)(m0 + lrow0) * Kd + lkc0 * 4];
    ra1 = *(const float4*)&A[(size_t)(m0 + lrow1) * Kd + lkc1 * 4];
    rw0 = *(const float4*)&W[(size_t)(n0 + lrow0) * Kd + lkc0 * 4];
    rw1 = *(const float4*)&W[(size_t)(n0 + lrow1) * Kd + lkc1 * 4];
    {
        float* a0 = &As[0][lkc0 * 4][lrow0];
        a0[0 * 132] = ra0.x; a0[1 * 132] = ra0.y; a0[2 * 132] = ra0.z; a0[3 * 132] = ra0.w;
        float* a1 = &As[0][lkc1 * 4][lrow1];
        a1[0 * 132] = ra1.x; a1[1 * 132] = ra1.y; a1[2 * 132] = ra1.z; a1[3 * 132] = ra1.w;
        float* w0 = &Ws[0][lkc0 * 4][lrow0];
        w0[0 * 132] = rw0.x; w0[1 * 132] = rw0.y; w0[2 * 132] = rw0.z; w0[3 * 132] = rw0.w;
        float* w1 = &Ws[0][lkc1 * 4][lrow1];
        w1[0 * 132] = rw1.x; w1[1 * 132] = rw1.y; w1[2 * 132] = rw1.z; w1[3 * 132] = rw1.w;
    }
    __syncthreads();

    int nK = Kd / 16;
    for (int kt = 0; kt < nK; kt++) {
        int buf = kt & 1;
        if (kt + 1 < nK) {
            int k0 = (kt + 1) * 16;
            ra0 = *(const float4*)&A[(size_t)(m0 + lrow0) * Kd + k0 + lkc0 * 4];
            ra1 = *(const float4*)&A[(size_t)(m0 + lrow1) * Kd + k0 + lkc1 * 4];
            rw0 = *(const float4*)&W[(size_t)(n0 + lrow0) * Kd + k0 + lkc0 * 4];
            rw1 = *(const float4*)&W[(size_t)(n0 + lrow1) * Kd + k0 + lkc1 * 4];
        }
        #pragma unroll
        for (int k = 0; k < 16; k++) {
            float4 a0 = *(const float4*)&As[buf][k][tm0];
            float4 a1 = *(const float4*)&As[buf][k][tm0 + 4];
            ulonglong2 wA = *(const ulonglong2*)&Ws[buf][k][tn0];
            ulonglong2 wB = *(const ulonglong2*)&Ws[buf][k][tn0 + 4];
            unsigned long long wp[4] = {wA.x, wA.y, wB.x, wB.y};
            float av[8] = {a0.x, a0.y, a0.z, a0.w, a1.x, a1.y, a1.z, a1.w};
            #pragma unroll
            for (int i = 0; i < 8; i++) {
                unsigned long long ad = pack2(av[i], av[i]);
                #pragma unroll
                for (int j = 0; j < 4; j++)
                    fma2(acc2[i][j], ad, wp[j]);
            }
        }
        if (kt + 1 < nK) {
            int nbuf = buf ^ 1;
            float* a0 = &As[nbuf][lkc0 * 4][lrow0];
            a0[0 * 132] = ra0.x; a0[1 * 132] = ra0.y; a0[2 * 132] = ra0.z; a0[3 * 132] = ra0.w;
            float* a1 = &As[nbuf][lkc1 * 4][lrow1];
            a1[0 * 132] = ra1.x; a1[1 * 132] = ra1.y; a1[2 * 132] = ra1.z; a1[3 * 132] = ra1.w;
            float* w0 = &Ws[nbuf][lkc0 * 4][lrow0];
            w0[0 * 132] = rw0.x; w0[1 * 132] = rw0.y; w0[2 * 132] = rw0.z; w0[3 * 132] = rw0.w;
            float* w1 = &Ws[nbuf][lkc1 * 4][lrow1];
            w1[0 * 132] = rw1.x; w1[1 * 132] = rw1.y; w1[2 * 132] = rw1.z; w1[3 * 132] = rw1.w;
        }
        __syncthreads();
    }

    int b = m0 >> 9;
    int t0 = m0 & 511;
    #pragma unroll
    for (int i = 0; i < 8; i++) {
        int t = t0 + tm0 + i;
        #pragma unroll
        for (int j = 0; j < 4; j++) {
            float2 c = unpack2(acc2[i][j]);
            int n = n0 + tn0 + 2 * j;
            C[((size_t)t * G + n) * B + b] = c.x + bias[n];
            C[((size_t)t * G + n + 1) * B + b] = c.y + bias[n + 1];
        }
    }
}

// ------------------------- per-direction grid barrier -------------------------
__device__ __forceinline__ void grid_barrier_dir(int dir) {
    __syncthreads();
    if (threadIdx.x == 0) {
        __threadfence();
        volatile unsigned* gv = &g_bargen2[dir];
        unsigned gen = *gv;
        unsigned ticket = atomicAdd(&g_barcnt2[dir], 1);
        if ((ticket + 1u) % 64u == 0u) {
            atomicAdd(&g_bargen2[dir], 1u);
        } else {
            while (*gv == gen) { }
        }
        __threadfence();
    }
    __syncthreads();
}

// ------------------------- persistent bidirectional LSTM layer ---------------
// Block bx: dir = bx>>6, h-slice h0 = (bx&63)*8.
// Compute mapping: warp w owns batches 8w..8w+7; lane l owns weight row
// (gate = l>>3, hidx = l&7). Per k: 1 LDS.32 weights (distinct, 128B/warp)
// + 2 LDS.128 h broadcasts (16B each) + 4 fma2. h no longer replicated
// across warps -> crossbar 2176 -> 1280 B/k/block.
// Gates staged via gsm for the pointwise (which keeps c in registers).
__global__ __launch_bounds__(256, 1)
void lstm_layer_kernel(const float* __restrict__ whh_f,
                       const float* __restrict__ whh_b, int layer) {
    extern __shared__ float sm[];
    float* ws  = sm;                        // [512][WKP], col = gate*8+hidx
    float* hs  = ws + 512 * WKP;            // [2][256*64]
    float* gsm = hs + 2 * 256 * 64;         // [32][66]

    int tid = threadIdx.x;
    int bx = blockIdx.x;
    int dir = bx >> 6;
    int h0 = (bx & 63) * 8;
    const float* __restrict__ Wm = dir ? whh_b : whh_f;
    const float* __restrict__ xg = g_xg[dir];
    float* __restrict__ hout = layer ? g_h1 : g_h0;

    int lane = tid & 31;
    int wrp = tid >> 5;         // warp: batches 8*wrp..8*wrp+7
    int ty = wrp;               // pointwise role: hidx = ty
    int b0 = lane * 2;          // pointwise role: batch pair

    unsigned hs_u32 = smem_u32(hs);

    // ---- load + transpose weights into SMEM (once); col = gate*8+hidx ----
    {
        int r = tid >> 3;                   // 0..31 = gate*8 + hidx
        int gate = r >> 3;
        int hidx = r & 7;
        int n = gate * H + h0 + hidx;
        const float* wrow = &Wm[(size_t)n * H];
        #pragma unroll
        for (int it = 0; it < 16; it++) {
            int kc4 = (tid & 7) + it * 8;   // float4 idx 0..127
            float4 w = *(const float4*)&wrow[kc4 * 4];
            float* d = &ws[(kc4 * 4) * WKP + r];
            d[0 * WKP] = w.x; d[1 * WKP] = w.y; d[2 * WKP] = w.z; d[3 * WKP] = w.w;
        }
    }

    // zero parity-0 h slice
    {
        float* z = g_hbuf[dir][0];
        for (int i = tid; i < 8 * 64; i += 256) z[h0 * 64 + i] = 0.0f;
    }
    float c_reg0 = 0.0f, c_reg1 = 0.0f;     // c for (hidx=ty, b0), (ty, b0+1)
    grid_barrier_dir(dir);

    for (int s = 0; s < T; s++) {
        int p = s & 1;
        int t = dir ? (T - 1 - s) : s;
        const float* __restrict__ hcur = g_hbuf[dir][p];
        float* __restrict__ hnext = g_hbuf[dir][p ^ 1];

        // xg prefetch for pointwise role: 4 gates x (b0, b0+1) of hidx=ty
        float2 xv[4];
        #pragma unroll
        for (int g = 0; g < 4; g++)
            xv[g] = __ldg((const float2*)&xg[((size_t)t * G + g * H + h0 + ty) * B + b0]);

        // stage both 256-k chunks (double buffered)
        #pragma unroll
        for (int j = 0; j < 16; j++) {
            int f4 = tid + j * 256;
            cp_async16(hs_u32 + f4 * 16, &hcur[f4 * 4]);
        }
        cp_commit();
        #pragma unroll
        for (int j = 0; j < 16; j++) {
            int f4 = tid + j * 256;
            cp_async16(hs_u32 + (16384 + f4 * 4) * 4, &hcur[16384 + f4 * 4]);
        }
        cp_commit();

        unsigned long long acc2[4] = {};    // batches (8w+2j, 8w+2j+1), this lane's (gate,hidx)

        #pragma unroll
        for (int c = 0; c < 2; c++) {
            if (c == 0) { cp_wait<1>(); } else { cp_wait<0>(); }
            __syncthreads();

            const float* hb = &hs[c * 16384];
            const float* wb = &ws[(c * 256) * WKP];
            #pragma unroll 4
            for (int k = 0; k < 256; k++) {
                ulonglong2 h01 = *(const ulonglong2*)&hb[k * 64 + 8 * wrp];
                ulonglong2 h23 = *(const ulonglong2*)&hb[k * 64 + 8 * wrp + 4];
                float wv = wb[k * WKP + lane];
                unsigned long long wd = pack2(wv, wv);
                fma2(acc2[0], wd, h01.x);
                fma2(acc2[1], wd, h01.y);
                fma2(acc2[2], wd, h23.x);
                fma2(acc2[3], wd, h23.y);
            }
        }

        // stage gates: gsm[gate*8+hidx][batch]
        #pragma unroll
        for (int j = 0; j < 4; j++)
            *(unsigned long long*)&gsm[lane * 66 + 8 * wrp + 2 * j] = acc2[j];
        __syncthreads();

        // pointwise in registers (thread = (hidx=ty, batches b0, b0+1))
        float2 gv0 = *(const float2*)&gsm[(0 * 8 + ty) * 66 + b0];
        float2 gv1 = *(const float2*)&gsm[(1 * 8 + ty) * 66 + b0];
        float2 gv2 = *(const float2*)&gsm[(2 * 8 + ty) * 66 + b0];
        float2 gv3 = *(const float2*)&gsm[(3 * 8 + ty) * 66 + b0];

        float gi0 = gv0.x + xv[0].x, gf0 = gv1.x + xv[1].x;
        float gc0 = gv2.x + xv[2].x, go0 = gv3.x + xv[3].x;
        float gi1 = gv0.y + xv[0].y, gf1 = gv1.y + xv[1].y;
        float gc1 = gv2.y + xv[2].y, go1 = gv3.y + xv[3].y;

        float si0 = 1.0f / (1.0f + expf(-gi0));
        float sf0 = 1.0f / (1.0f + expf(-gf0));
        float so0 = 1.0f / (1.0f + expf(-go0));
        float si1 = 1.0f / (1.0f + expf(-gi1));
        float sf1 = 1.0f / (1.0f + expf(-gf1));
        float so1 = 1.0f / (1.0f + expf(-go1));

        c_reg0 = sf0 * c_reg0 + si0 * tanhf(gc0);
        c_reg1 = sf1 * c_reg1 + si1 * tanhf(gc1);
        float hn0 = so0 * tanhf(c_reg0);
        float hn1 = so1 * tanhf(c_reg1);

        *(float2*)&hnext[(h0 + ty) * 64 + b0] = make_float2(hn0, hn1);
        size_t ob = ((size_t)b0 * T + t) * H2 + dir * H + h0 + ty;
        hout[ob] = hn0;
        hout[ob + (size_t)T * H2] = hn1;    // b0+1

        grid_barrier_dir(dir);
    }
}

// ------------------------- output projection (K=24) --------------------------
__global__ __launch_bounds__(256)
void proj_kernel(const float* __restrict__ w_out, const float* __restrict__ b_out) {
    int bt = blockIdx.x;
    int wid = threadIdx.x >> 5;
    int lane = threadIdx.x & 31;
    const float* hrow = g_h1 + (long long)bt * H2;

    for (int j = wid; j < K; j += 8) {
        const float* wr = w_out + j * H2;
        float s = 0.0f;
        for (int k = lane; k < H2; k += 32)
            s += hrow[k] * wr[k];
        #pragma unroll
        for (int off = 16; off; off >>= 1)
            s += __shfl_xor_sync(0xffffffff, s, off);
        if (lane == 0)
            g_feats[bt * K + j] = s + b_out[j];
    }
}

// ------------------------- Viterbi decode ------------------------------------
__global__ void viterbi_kernel(const float* __restrict__ trans,
                               float* __restrict__ out, int out_size) {
    int b = blockIdx.x;
    int tid = threadIdx.x;

    __shared__ float tr[K][K];
    __shared__ float v[K];
    __shared__ float vn[K];
    __shared__ unsigned char bp[T][K];

    for (int i = tid; i < K * K; i += 32)
        tr[i / K][i % K] = trans[i];
    if (tid < K)
        v[tid] = (tid == START_TAG) ? 0.0f : NEG;
    __syncthreads();

    for (int t = 0; t < T; t++) {
        if (tid < K) {
            float best = -3.4e38f;
            int arg = 0;
            #pragma unroll
            for (int kp = 0; kp < K; kp++) {
                float sc = v[kp] + tr[tid][kp];
                if (sc > best) { best = sc; arg = kp; }
            }
            vn[tid] = best + g_feats[(b * T + t) * K + tid];
            bp[t][tid] = (unsigned char)arg;
        }
        __syncthreads();
        if (tid < K) v[tid] = vn[tid];
        __syncthreads();
    }

    if (tid == 0) {
        float best = -3.4e38f;
        int arg = 0;
        for (int k = 0; k < K; k++) {
            float sc = v[k] + tr[STOP_TAG][k];
            if (sc > best) { best = sc; arg = k; }
        }
        if (out_size >= B + B * T) {
            out[b] = best;
            int tag = arg;
            for (int t = T - 1; t >= 0; t--) {
                out[B + b * T + t] = (float)tag;
                tag = bp[t][tag];
            }
        } else if (out_size >= B * T) {
            int tag = arg;
            for (int t = T - 1; t >= 0; t--) {
                out[b * T + t] = (float)tag;
                tag = bp[t][tag];
            }
        } else {
            out[b] = best;
        }
    }
}

// ------------------------- launch --------------------------------------------
extern "C" void kernel_launch(void* const* d_in, const int* in_sizes, int n_in,
                              void* d_out, int out_size) {
    const int*   sentence = (const int*)d_in[0];
    const float* embed    = (const float*)d_in[1];
    const float* w_ih_l0f = (const float*)d_in[2];
    const float* w_hh_l0f = (const float*)d_in[3];
    const float* b_l0f    = (const float*)d_in[4];
    const float* w_ih_l0b = (const float*)d_in[5];
    const float* w_hh_l0b = (const float*)d_in[6];
    const float* b_l0b    = (const float*)d_in[7];
    const float* w_ih_l1f = (const float*)d_in[8];
    const float* w_hh_l1f = (const float*)d_in[9];
    const float* b_l1f    = (const float*)d_in[10];
    const float* w_ih_l1b = (const float*)d_in[11];
    const float* w_hh_l1b = (const float*)d_in[12];
    const float* b_l1b    = (const float*)d_in[13];
    const float* w_out    = (const float*)d_in[14];
    const float* b_out    = (const float*)d_in[15];
    const float* trans    = (const float*)d_in[16];
    float* out = (float*)d_out;

    const int lstm_smem = (512 * WKP + 2 * 256 * 64 + 32 * 66) * 4;   // 213248 B
    cudaFuncSetAttribute(lstm_layer_kernel,
                         cudaFuncAttributeMaxDynamicSharedMemorySize, lstm_smem);

    // 1. embedding
    embed_kernel<<<(B * T * E + 255) / 256, 256>>>(sentence, embed);

    // 2. layer-0 input-gate GEMMs (Kd=256)
    dim3 ggrid(G / 128, M_ROWS / 128);
    gemm_bias_kernel<<<ggrid, 256>>>(0, w_ih_l0f, b_l0f, 0, E);
    gemm_bias_kernel<<<ggrid, 256>>>(0, w_ih_l0b, b_l0b, 1, E);

    // 3. layer-0 recurrence (persistent)
    lstm_layer_kernel<<<NBLK, 256, lstm_smem>>>(w_hh_l0f, w_hh_l0b, 0);

    // 4. layer-1 input-gate GEMMs (Kd=1024)
    gemm_bias_kernel<<<ggrid, 256>>>(1, w_ih_l1f, b_l1f, 0, H2);
    gemm_bias_kernel<<<ggrid, 256>>>(1, w_ih_l1b, b_l1b, 1, H2);

    // 5. layer-1 recurrence
    lstm_layer_kernel<<<NBLK, 256, lstm_smem>>>(w_hh_l1f, w_hh_l1b, 1);

    // 6. emission features
    proj_kernel<<<B * T, 256>>>(w_out, b_out);

    // 7. Viterbi decode + output
    viterbi_kernel<<<B, 32>>>(trans, out, out_size);
}

// round 15
// speedup vs baseline: 1.1291x; 1.1291x over previous
#include <cuda_runtime.h>
#include <math.h>

// Problem constants
constexpr int B = 64;
constexpr int T = 512;
constexpr int E = 256;
constexpr int H = 512;
constexpr int K = 24;
constexpr int G = 4 * H;          // 2048
constexpr int H2 = 2 * H;         // 1024
constexpr int START_TAG = 22;
constexpr int STOP_TAG = 23;
constexpr float NEG = -10000.0f;
constexpr int M_ROWS = B * T;     // 32768

constexpr int NBLK = 128;         // persistent recurrence blocks (64 per dir)
constexpr int WKP = 36;           // ws row stride (floats)

// ------------------------- device scratch (static, no allocs) ----------------
__device__ float g_x[B * T * E];
__device__ float g_xg[2][T * G * B];          // [dir][(t*G+n)*B + b]
__device__ float g_h0[B * T * H2];
__device__ float g_h1[B * T * H2];
__device__ float g_hbuf[2][2][H * B];         // [dir][parity][k*64+b]
__device__ float g_feats[B * T * K];
__device__ unsigned g_barcnt2[2];
__device__ unsigned g_bargen2[2];

// ------------------------- small helpers -------------------------------------
static __device__ __forceinline__ unsigned smem_u32(const void* p) {
    unsigned r;
    asm("{ .reg .u64 t; cvta.to.shared.u64 t, %1; cvt.u32.u64 %0, t; }"
        : "=r"(r) : "l"(p));
    return r;
}
static __device__ __forceinline__ void cp_async16(unsigned dst, const void* src) {
    asm volatile("cp.async.cg.shared.global [%0], [%1], 16;\n" :: "r"(dst), "l"(src));
}
static __device__ __forceinline__ void cp_commit() {
    asm volatile("cp.async.commit_group;\n" ::: "memory");
}
template <int N>
static __device__ __forceinline__ void cp_wait() {
    asm volatile("cp.async.wait_group %0;\n" :: "n"(N) : "memory");
}
static __device__ __forceinline__ void named_bar(int id, int nthreads) {
    asm volatile("bar.sync %0, %1;" :: "r"(id), "r"(nthreads) : "memory");
}

// packed f32x2 helpers
static __device__ __forceinline__ unsigned long long pack2(float x, float y) {
    unsigned long long r;
    asm("mov.b64 %0, {%1, %2};" : "=l"(r) : "f"(x), "f"(y));
    return r;
}
static __device__ __forceinline__ void fma2(unsigned long long& d,
                                            unsigned long long a,
                                            unsigned long long b) {
    asm("fma.rn.f32x2 %0, %1, %2, %3;" : "=l"(d) : "l"(a), "l"(b), "l"(d));
}
static __device__ __forceinline__ float2 unpack2(unsigned long long v) {
    float2 f;
    asm("mov.b64 {%0, %1}, %2;" : "=f"(f.x), "=f"(f.y) : "l"(v));
    return f;
}

// ------------------------- embedding lookup ----------------------------------
__global__ void embed_kernel(const int* __restrict__ sentence,
                             const float* __restrict__ embed) {
    int i = blockIdx.x * blockDim.x + threadIdx.x;
    if (i >= B * T * E) return;
    int e = i % E;
    int bt = i / E;
    g_x[i] = embed[(long long)sentence[bt] * E + e];
}

// ------------------------- big GEMM: xg_t = A * W^T + bias (R13 verbatim) ----
__global__ __launch_bounds__(256)
void gemm_bias_kernel(int a_sel, const float* __restrict__ W,
                      const float* __restrict__ bias, int c_dir, int Kd) {
    const float* __restrict__ A = a_sel ? g_h0 : g_x;
    float* __restrict__ C = g_xg[c_dir];

    __shared__ float As[2][16][132];
    __shared__ float Ws[2][16][132];

    int n0 = blockIdx.x * 128;
    int m0 = blockIdx.y * 128;
    int tid = threadIdx.x;
    int tx = tid & 15;
    int ty = tid >> 4;
    int tm0 = ty * 8;
    int tn0 = tx * 8;

    int lrow0 = (tid * 2) >> 2;
    int lkc0 = (tid * 2) & 3;
    int lrow1 = (tid * 2 + 1) >> 2;
    int lkc1 = (tid * 2 + 1) & 3;

    unsigned long long acc2[8][4] = {};
    float4 ra0, ra1, rw0, rw1;

    ra0 = *(const float4*)&A[(size_t)(m0 + lrow0) * Kd + lkc0 * 4];
    ra1 = *(const float4*)&A[(size_t)(m0 + lrow1) * Kd + lkc1 * 4];
    rw0 = *(const float4*)&W[(size_t)(n0 + lrow0) * Kd + lkc0 * 4];
    rw1 = *(const float4*)&W[(size_t)(n0 + lrow1) * Kd + lkc1 * 4];
    {
        float* a0 = &As[0][lkc0 * 4][lrow0];
        a0[0 * 132] = ra0.x; a0[1 * 132] = ra0.y; a0[2 * 132] = ra0.z; a0[3 * 132] = ra0.w;
        float* a1 = &As[0][lkc1 * 4][lrow1];
        a1[0 * 132] = ra1.x; a1[1 * 132] = ra1.y; a1[2 * 132] = ra1.z; a1[3 * 132] = ra1.w;
        float* w0 = &Ws[0][lkc0 * 4][lrow0];
        w0[0 * 132] = rw0.x; w0[1 * 132] = rw0.y; w0[2 * 132] = rw0.z; w0[3 * 132] = rw0.w;
        float* w1 = &Ws[0][lkc1 * 4][lrow1];
        w1[0 * 132] = rw1.x; w1[1 * 132] = rw1.y; w1[2 * 132] = rw1.z; w1[3 * 132] = rw1.w;
    }
    __syncthreads();

    int nK = Kd / 16;
    for (int kt = 0; kt < nK; kt++) {
        int buf = kt & 1;
        if (kt + 1 < nK) {
            int k0 = (kt + 1) * 16;
            ra0 = *(const float4*)&A[(size_t)(m0 + lrow0) * Kd + k0 + lkc0 * 4];
            ra1 = *(const float4*)&A[(size_t)(m0 + lrow1) * Kd + k0 + lkc1 * 4];
            rw0 = *(const float4*)&W[(size_t)(n0 + lrow0) * Kd + k0 + lkc0 * 4];
            rw1 = *(const float4*)&W[(size_t)(n0 + lrow1) * Kd + k0 + lkc1 * 4];
        }
        #pragma unroll
        for (int k = 0; k < 16; k++) {
            float4 a0 = *(const float4*)&As[buf][k][tm0];
            float4 a1 = *(const float4*)&As[buf][k][tm0 + 4];
            ulonglong2 wA = *(const ulonglong2*)&Ws[buf][k][tn0];
            ulonglong2 wB = *(const ulonglong2*)&Ws[buf][k][tn0 + 4];
            unsigned long long wp[4] = {wA.x, wA.y, wB.x, wB.y};
            float av[8] = {a0.x, a0.y, a0.z, a0.w, a1.x, a1.y, a1.z, a1.w};
            #pragma unroll
            for (int i = 0; i < 8; i++) {
                unsigned long long ad = pack2(av[i], av[i]);
                #pragma unroll
                for (int j = 0; j < 4; j++)
                    fma2(acc2[i][j], ad, wp[j]);
            }
        }
        if (kt + 1 < nK) {
            int nbuf = buf ^ 1;
            float* a0 = &As[nbuf][lkc0 * 4][lrow0];
            a0[0 * 132] = ra0.x; a0[1 * 132] = ra0.y; a0[2 * 132] = ra0.z; a0[3 * 132] = ra0.w;
            float* a1 = &As[nbuf][lkc1 * 4][lrow1];
            a1[0 * 132] = ra1.x; a1[1 * 132] = ra1.y; a1[2 * 132] = ra1.z; a1[3 * 132] = ra1.w;
            float* w0 = &Ws[nbuf][lkc0 * 4][lrow0];
            w0[0 * 132] = rw0.x; w0[1 * 132] = rw0.y; w0[2 * 132] = rw0.z; w0[3 * 132] = rw0.w;
            float* w1 = &Ws[nbuf][lkc1 * 4][lrow1];
            w1[0 * 132] = rw1.x; w1[1 * 132] = rw1.y; w1[2 * 132] = rw1.z; w1[3 * 132] = rw1.w;
        }
        __syncthreads();
    }

    int b = m0 >> 9;
    int t0 = m0 & 511;
    #pragma unroll
    for (int i = 0; i < 8; i++) {
        int t = t0 + tm0 + i;
        #pragma unroll
        for (int j = 0; j < 4; j++) {
            float2 c = unpack2(acc2[i][j]);
            int n = n0 + tn0 + 2 * j;
            C[((size_t)t * G + n) * B + b] = c.x + bias[n];
            C[((size_t)t * G + n + 1) * B + b] = c.y + bias[n + 1];
        }
    }
}

// ------------------------- per-direction grid barrier -------------------------
__device__ __forceinline__ void grid_barrier_dir(int dir) {
    __syncthreads();
    if (threadIdx.x == 0) {
        __threadfence();
        volatile unsigned* gv = &g_bargen2[dir];
        unsigned gen = *gv;
        unsigned ticket = atomicAdd(&g_barcnt2[dir], 1);
        if ((ticket + 1u) % 64u == 0u) {
            atomicAdd(&g_bargen2[dir], 1u);
        } else {
            while (*gv == gen) { }
        }
        __threadfence();
    }
    __syncthreads();
}

// ------------------------- persistent bidirectional LSTM layer ---------------
// Block bx: dir = bx>>6, h-slice h0 = (bx&63)*8.
// Split-k warp specialization: warpgroup wg = tid>>7 handles k in
// [wg*256, wg*256+256). Within a group, warp w4 owns h-index pair
// (2*w4, 2*w4+1); lane owns batch pair. Per k: 2 LDS.128 w-broadcast +
// 1 LDS.64 h + 2 packs + 8 fma2 = 13 instr / 16 MAC. Each group stages only
// its own k-chunk and syncs on a 128-thread named barrier. Partial gate sums
// reduced through gsmA/gsmB [32][66]; pointwise keeps c in registers.
__global__ __launch_bounds__(256, 1)
void lstm_layer_kernel(const float* __restrict__ whh_f,
                       const float* __restrict__ whh_b, int layer) {
    extern __shared__ float sm[];
    float* ws   = sm;                       // [512][WKP], col = hidx*4+gate
    float* hs   = ws + 512 * WKP;           // [2][256*64]
    float* gsmA = hs + 2 * 256 * 64;        // [32][66] partials group 0
    float* gsmB = gsmA + 32 * 66;           // [32][66] partials group 1

    int tid = threadIdx.x;
    int bx = blockIdx.x;
    int dir = bx >> 6;
    int h0 = (bx & 63) * 8;
    const float* __restrict__ Wm = dir ? whh_b : whh_f;
    const float* __restrict__ xg = g_xg[dir];
    float* __restrict__ hout = layer ? g_h1 : g_h0;

    int lane = tid & 31;
    int wrp = tid >> 5;
    int wg = tid >> 7;          // k-half (0 or 1)
    int w4 = wrp & 3;           // h-index pair within group
    int ty = wrp;               // pointwise role: hidx = ty (0..7)
    int b0 = lane * 2;          // batch pair (both roles)
    int qA = 8 * w4;            // ws col base: hidx 2*w4 (4 gates)
    float* gsm_my = wg ? gsmB : gsmA;

    unsigned hs_u32 = smem_u32(hs);

    // ---- load + transpose weights into SMEM (once); col = hidx*4+gate ----
    {
        int r = tid >> 3;                   // 0..31 = gate*8 + hidx
        int gate = r >> 3;
        int hidx = r & 7;
        int q = hidx * 4 + gate;
        int n = gate * H + h0 + hidx;
        const float* wrow = &Wm[(size_t)n * H];
        #pragma unroll
        for (int it = 0; it < 16; it++) {
            int kc4 = (tid & 7) + it * 8;   // float4 idx 0..127
            float4 w = *(const float4*)&wrow[kc4 * 4];
            float* d = &ws[(kc4 * 4) * WKP + q];
            d[0 * WKP] = w.x; d[1 * WKP] = w.y; d[2 * WKP] = w.z; d[3 * WKP] = w.w;
        }
    }

    // zero parity-0 h slice
    {
        float* z = g_hbuf[dir][0];
        for (int i = tid; i < 8 * 64; i += 256) z[h0 * 64 + i] = 0.0f;
    }
    float c_reg0 = 0.0f, c_reg1 = 0.0f;     // c for (hidx=ty, b0), (ty, b0+1)
    grid_barrier_dir(dir);

    for (int s = 0; s < T; s++) {
        int p = s & 1;
        int t = dir ? (T - 1 - s) : s;
        const float* __restrict__ hcur = g_hbuf[dir][p];
        float* __restrict__ hnext = g_hbuf[dir][p ^ 1];

        // xg prefetch for pointwise role: 4 gates x (b0, b0+1) of hidx=ty
        float2 xv[4];
        #pragma unroll
        for (int g = 0; g < 4; g++)
            xv[g] = __ldg((const float2*)&xg[((size_t)t * G + g * H + h0 + ty) * B + b0]);

        // each group stages ONLY its own 256-k chunk (4096 float4 / 128 thr)
        {
            int tl = tid & 127;
            const float* src = hcur + wg * 16384;
            unsigned dst = hs_u32 + wg * 16384 * 4;
            #pragma unroll
            for (int j = 0; j < 32; j++) {
                int f4 = tl + j * 128;
                cp_async16(dst + f4 * 16, src + f4 * 4);
            }
            cp_commit();
            cp_wait<0>();
            named_bar(1 + wg, 128);         // group-local barrier
        }

        // compute this group's k-half
        unsigned long long a0 = 0, a1 = 0, a2 = 0, a3 = 0;   // b0:  hidxA(g01,g23), hidxB(g01,g23)
        unsigned long long a4 = 0, a5 = 0, a6 = 0, a7 = 0;   // b0+1 same
        {
            const float* hb = &hs[wg * 16384];
            const float* wb = &ws[(wg * 256) * WKP];
            #pragma unroll 4
            for (int k = 0; k < 256; k++) {
                ulonglong2 wA = *(const ulonglong2*)&wb[k * WKP + qA];
                ulonglong2 wB = *(const ulonglong2*)&wb[k * WKP + qA + 4];
                float2 h = *(const float2*)&hb[k * 64 + b0];
                unsigned long long hx = pack2(h.x, h.x);
                unsigned long long hy = pack2(h.y, h.y);
                fma2(a0, wA.x, hx); fma2(a1, wA.y, hx);
                fma2(a2, wB.x, hx); fma2(a3, wB.y, hx);
                fma2(a4, wA.x, hy); fma2(a5, wA.y, hy);
                fma2(a6, wB.x, hy); fma2(a7, wB.y, hy);
            }
        }

        // store partials: gsm[col][b], col = hidx*4+gate
        {
            float2 f0 = unpack2(a0), f1 = unpack2(a1);
            float2 f2 = unpack2(a2), f3 = unpack2(a3);
            float2 f4 = unpack2(a4), f5 = unpack2(a5);
            float2 f6 = unpack2(a6), f7 = unpack2(a7);
            gsm_my[(qA + 0) * 66 + b0] = f0.x;  gsm_my[(qA + 1) * 66 + b0] = f0.y;
            gsm_my[(qA + 2) * 66 + b0] = f1.x;  gsm_my[(qA + 3) * 66 + b0] = f1.y;
            gsm_my[(qA + 4) * 66 + b0] = f2.x;  gsm_my[(qA + 5) * 66 + b0] = f2.y;
            gsm_my[(qA + 6) * 66 + b0] = f3.x;  gsm_my[(qA + 7) * 66 + b0] = f3.y;
            gsm_my[(qA + 0) * 66 + b0 + 1] = f4.x;  gsm_my[(qA + 1) * 66 + b0 + 1] = f4.y;
            gsm_my[(qA + 2) * 66 + b0 + 1] = f5.x;  gsm_my[(qA + 3) * 66 + b0 + 1] = f5.y;
            gsm_my[(qA + 4) * 66 + b0 + 1] = f6.x;  gsm_my[(qA + 5) * 66 + b0 + 1] = f6.y;
            gsm_my[(qA + 6) * 66 + b0 + 1] = f7.x;  gsm_my[(qA + 7) * 66 + b0 + 1] = f7.y;
        }
        __syncthreads();

        // pointwise (thread = hidx ty, batches b0, b0+1); reduce the 2 k-halves
        float2 gv[4];
        #pragma unroll
        for (int g = 0; g < 4; g++) {
            float2 pa = *(const float2*)&gsmA[(ty * 4 + g) * 66 + b0];
            float2 pb = *(const float2*)&gsmB[(ty * 4 + g) * 66 + b0];
            gv[g] = make_float2(pa.x + pb.x, pa.y + pb.y);
        }

        float gi0 = gv[0].x + xv[0].x, gf0 = gv[1].x + xv[1].x;
        float gc0 = gv[2].x + xv[2].x, go0 = gv[3].x + xv[3].x;
        float gi1 = gv[0].y + xv[0].y, gf1 = gv[1].y + xv[1].y;
        float gc1 = gv[2].y + xv[2].y, go1 = gv[3].y + xv[3].y;

        float si0 = 1.0f / (1.0f + expf(-gi0));
        float sf0 = 1.0f / (1.0f + expf(-gf0));
        float so0 = 1.0f / (1.0f + expf(-go0));
        float si1 = 1.0f / (1.0f + expf(-gi1));
        float sf1 = 1.0f / (1.0f + expf(-gf1));
        float so1 = 1.0f / (1.0f + expf(-go1));

        c_reg0 = sf0 * c_reg0 + si0 * tanhf(gc0);
        c_reg1 = sf1 * c_reg1 + si1 * tanhf(gc1);
        float hn0 = so0 * tanhf(c_reg0);
        float hn1 = so1 * tanhf(c_reg1);

        *(float2*)&hnext[(h0 + ty) * 64 + b0] = make_float2(hn0, hn1);
        size_t ob = ((size_t)b0 * T + t) * H2 + dir * H + h0 + ty;
        hout[ob] = hn0;
        hout[ob + (size_t)T * H2] = hn1;    // b0+1

        grid_barrier_dir(dir);
    }
}

// ------------------------- output projection (K=24) --------------------------
__global__ __launch_bounds__(256)
void proj_kernel(const float* __restrict__ w_out, const float* __restrict__ b_out) {
    int bt = blockIdx.x;
    int wid = threadIdx.x >> 5;
    int lane = threadIdx.x & 31;
    const float* hrow = g_h1 + (long long)bt * H2;

    for (int j = wid; j < K; j += 8) {
        const float* wr = w_out + j * H2;
        float s = 0.0f;
        for (int k = lane; k < H2; k += 32)
            s += hrow[k] * wr[k];
        #pragma unroll
        for (int off = 16; off; off >>= 1)
            s += __shfl_xor_sync(0xffffffff, s, off);
        if (lane == 0)
            g_feats[bt * K + j] = s + b_out[j];
    }
}

// ------------------------- Viterbi decode ------------------------------------
__global__ void viterbi_kernel(const float* __restrict__ trans,
                               float* __restrict__ out, int out_size) {
    int b = blockIdx.x;
    int tid = threadIdx.x;

    __shared__ float tr[K][K];
    __shared__ float v[K];
    __shared__ float vn[K];
    __shared__ unsigned char bp[T][K];

    for (int i = tid; i < K * K; i += 32)
        tr[i / K][i % K] = trans[i];
    if (tid < K)
        v[tid] = (tid == START_TAG) ? 0.0f : NEG;
    __syncthreads();

    for (int t = 0; t < T; t++) {
        if (tid < K) {
            float best = -3.4e38f;
            int arg = 0;
            #pragma unroll
            for (int kp = 0; kp < K; kp++) {
                float sc = v[kp] + tr[tid][kp];
                if (sc > best) { best = sc; arg = kp; }
            }
            vn[tid] = best + g_feats[(b * T + t) * K + tid];
            bp[t][tid] = (unsigned char)arg;
        }
        __syncthreads();
        if (tid < K) v[tid] = vn[tid];
        __syncthreads();
    }

    if (tid == 0) {
        float best = -3.4e38f;
        int arg = 0;
        for (int k = 0; k < K; k++) {
            float sc = v[k] + tr[STOP_TAG][k];
            if (sc > best) { best = sc; arg = k; }
        }
        if (out_size >= B + B * T) {
            out[b] = best;
            int tag = arg;
            for (int t = T - 1; t >= 0; t--) {
                out[B + b * T + t] = (float)tag;
                tag = bp[t][tag];
            }
        } else if (out_size >= B * T) {
            int tag = arg;
            for (int t = T - 1; t >= 0; t--) {
                out[b * T + t] = (float)tag;
                tag = bp[t][tag];
            }
        } else {
            out[b] = best;
        }
    }
}

// ------------------------- launch --------------------------------------------
extern "C" void kernel_launch(void* const* d_in, const int* in_sizes, int n_in,
                              void* d_out, int out_size) {
    const int*   sentence = (const int*)d_in[0];
    const float* embed    = (const float*)d_in[1];
    const float* w_ih_l0f = (const float*)d_in[2];
    const float* w_hh_l0f = (const float*)d_in[3];
    const float* b_l0f    = (const float*)d_in[4];
    const float* w_ih_l0b = (const float*)d_in[5];
    const float* w_hh_l0b = (const float*)d_in[6];
    const float* b_l0b    = (const float*)d_in[7];
    const float* w_ih_l1f = (const float*)d_in[8];
    const float* w_hh_l1f = (const float*)d_in[9];
    const float* b_l1f    = (const float*)d_in[10];
    const float* w_ih_l1b = (const float*)d_in[11];
    const float* w_hh_l1b = (const float*)d_in[12];
    const float* b_l1b    = (const float*)d_in[13];
    const float* w_out    = (const float*)d_in[14];
    const float* b_out    = (const float*)d_in[15];
    const float* trans    = (const float*)d_in[16];
    float* out = (float*)d_out;

    const int lstm_smem = (512 * WKP + 2 * 256 * 64 + 2 * 32 * 66) * 4;  // 221568 B
    cudaFuncSetAttribute(lstm_layer_kernel,
                         cudaFuncAttributeMaxDynamicSharedMemorySize, lstm_smem);

    // 1. embedding
    embed_kernel<<<(B * T * E + 255) / 256, 256>>>(sentence, embed);

    // 2. layer-0 input-gate GEMMs (Kd=256)
    dim3 ggrid(G / 128, M_ROWS / 128);
    gemm_bias_kernel<<<ggrid, 256>>>(0, w_ih_l0f, b_l0f, 0, E);
    gemm_bias_kernel<<<ggrid, 256>>>(0, w_ih_l0b, b_l0b, 1, E);

    // 3. layer-0 recurrence (persistent)
    lstm_layer_kernel<<<NBLK, 256, lstm_smem>>>(w_hh_l0f, w_hh_l0b, 0);

    // 4. layer-1 input-gate GEMMs (Kd=1024)
    gemm_bias_kernel<<<ggrid, 256>>>(1, w_ih_l1f, b_l1f, 0, H2);
    gemm_bias_kernel<<<ggrid, 256>>>(1, w_ih_l1b, b_l1b, 1, H2);

    // 5. layer-1 recurrence
    lstm_layer_kernel<<<NBLK, 256, lstm_smem>>>(w_hh_l1f, w_hh_l1b, 1);

    // 6. emission features
    proj_kernel<<<B * T, 256>>>(w_out, b_out);

    // 7. Viterbi decode + output
    viterbi_kernel<<<B, 32>>>(trans, out, out_size);
}